// round 11
// baseline (speedup 1.0000x reference)
#include <cuda_runtime.h>
#include <cuda_bf16.h>
#include <cuda_fp16.h>
#include <math.h>
#include <stdint.h>

#define NN 20000
#define EE 160000
#define OUTD 256
#define INDIM 256
#define NH 8

typedef unsigned long long ull;

// ---------------- scratch (device globals; no allocation allowed) ----------------
__device__ __half g_Qh[(size_t)NN * OUTD];
__device__ __half g_Kh[(size_t)NN * OUTD];
__device__ __half g_Vh[(size_t)NN * OUTD];
__device__ __half g_MKh[(size_t)NN * OUTD];
__device__ __half g_VC[(size_t)3 * NN * 512];  // per (etype,node): [0,256)=val, [256,512)=cval
__device__ float2 g_E[3 * EE * NH];            // (ea, eca) per edge-head
__device__ float2 g_S[3 * NN * NH];            // (sum_ea, sum_eca) per dst-head
// bf16 hi/lo splits for tensor-core GEMM
__device__ __nv_bfloat16 g_xhi[NN * INDIM];
__device__ __nv_bfloat16 g_xlo[NN * INDIM];
__device__ __nv_bfloat16 g_wthi[768 * INDIM];   // [out_col][k] transposed
__device__ __nv_bfloat16 g_wtlo[768 * INDIM];

// ---------------- helpers ----------------
__device__ __forceinline__ ull pack2(float a, float b) {
    ull r; asm("mov.b64 %0, {%1, %2};" : "=l"(r) : "f"(a), "f"(b)); return r;
}
__device__ __forceinline__ void fma2(ull& acc, ull a, ull b) {
    asm("fma.rn.f32x2 %0, %1, %2, %0;" : "+l"(acc) : "l"(a), "l"(b));
}
__device__ __forceinline__ float2 unpack2(ull v) {
    float2 f; asm("mov.b64 {%0, %1}, %2;" : "=f"(f.x), "=f"(f.y) : "l"(v)); return f;
}
__device__ __forceinline__ void red_add_v4(float* p, float a, float b, float c, float d) {
    asm volatile("red.global.add.v4.f32 [%0], {%1,%2,%3,%4};"
                 :: "l"(p), "f"(a), "f"(b), "f"(c), "f"(d) : "memory");
}
__device__ __forceinline__ void red_add_v2(float2* p, float a, float b) {
    asm volatile("red.global.add.v2.f32 [%0], {%1,%2};"
                 :: "l"(p), "f"(a), "f"(b) : "memory");
}
__device__ __forceinline__ uint32_t smem_to_u32(const void* p) {
    uint32_t a;
    asm("{ .reg .u64 t; cvta.to.shared.u64 t, %1; cvt.u32.u64 %0, t; }" : "=r"(a) : "l"(p));
    return a;
}
__device__ __forceinline__ void ldsm_x4(uint32_t* r, uint32_t addr) {
    asm volatile("ldmatrix.sync.aligned.m8n8.x4.shared.b16 {%0,%1,%2,%3}, [%4];"
        : "=r"(r[0]), "=r"(r[1]), "=r"(r[2]), "=r"(r[3]) : "r"(addr));
}
__device__ __forceinline__ void mma_bf16(float* c, const uint32_t* a, const uint32_t* b) {
    asm volatile("mma.sync.aligned.m16n8k16.row.col.f32.bf16.bf16.f32 "
        "{%0,%1,%2,%3}, {%4,%5,%6,%7}, {%8,%9}, {%0,%1,%2,%3};"
        : "+f"(c[0]), "+f"(c[1]), "+f"(c[2]), "+f"(c[3])
        : "r"(a[0]), "r"(a[1]), "r"(a[2]), "r"(a[3]), "r"(b[0]), "r"(b[1]));
}
__device__ __forceinline__ void cp_async16(uint32_t dst, const void* src, int sz) {
    asm volatile("cp.async.ca.shared.global [%0], [%1], 16, %2;"
                 :: "r"(dst), "l"(src), "r"(sz) : "memory");
}
// dot of 8 fp16 pairs held in two uint4s (fp32 accumulation)
__device__ __forceinline__ float dot8h(uint4 a, uint4 b) {
    float2 a0 = __half22float2(*(__half2*)&a.x), b0 = __half22float2(*(__half2*)&b.x);
    float2 a1 = __half22float2(*(__half2*)&a.y), b1 = __half22float2(*(__half2*)&b.y);
    float2 a2 = __half22float2(*(__half2*)&a.z), b2 = __half22float2(*(__half2*)&b.z);
    float2 a3 = __half22float2(*(__half2*)&a.w), b3 = __half22float2(*(__half2*)&b.w);
    return a0.x * b0.x + a0.y * b0.y + a1.x * b1.x + a1.y * b1.y
         + a2.x * b2.x + a2.y * b2.y + a3.x * b3.x + a3.y * b3.y;
}
__device__ __forceinline__ void h8_to_f8(uint4 u, float* f) {
    float2 t;
    t = __half22float2(*(__half2*)&u.x); f[0] = t.x; f[1] = t.y;
    t = __half22float2(*(__half2*)&u.y); f[2] = t.x; f[3] = t.y;
    t = __half22float2(*(__half2*)&u.z); f[4] = t.x; f[5] = t.y;
    t = __half22float2(*(__half2*)&u.w); f[6] = t.x; f[7] = t.y;
}

// ---------------- kernel 0: zero accumulators ----------------
__global__ void zero_kernel(float* __restrict__ out) {
    int stride = gridDim.x * blockDim.x;
    for (int i = blockIdx.x * blockDim.x + threadIdx.x; i < NN * OUTD; i += stride)
        out[i] = 0.0f;
    float2 z2 = make_float2(0.f, 0.f);
    for (int i = blockIdx.x * blockDim.x + threadIdx.x; i < 3 * NN * NH; i += stride)
        g_S[i] = z2;
}

// ---------------- prep: fp32 -> bf16 hi/lo splits ----------------
__global__ void split_x_kernel(const float* __restrict__ x) {
    int i = blockIdx.x * blockDim.x + threadIdx.x;
    if (i >= NN * INDIM / 4) return;
    float4 v = ((const float4*)x)[i];
    __nv_bfloat16 h[4], l[4];
    float f[4] = {v.x, v.y, v.z, v.w};
#pragma unroll
    for (int j = 0; j < 4; j++) {
        h[j] = __float2bfloat16(f[j]);
        l[j] = __float2bfloat16(f[j] - __bfloat162float(h[j]));
    }
    ((uint2*)g_xhi)[i] = *(uint2*)h;
    ((uint2*)g_xlo)[i] = *(uint2*)l;
}

__global__ void split_w_kernel(const float* __restrict__ Wk,
                               const float* __restrict__ Wq,
                               const float* __restrict__ Wv) {
    int i = blockIdx.x * blockDim.x + threadIdx.x;   // i = c*256 + k
    if (i >= 768 * INDIM) return;
    int c = i >> 8, k = i & 255;
    const float* W = (c < 256) ? Wk : ((c < 512) ? Wq : Wv);
    float v = W[k * 256 + (c & 255)];
    __nv_bfloat16 h = __float2bfloat16(v);
    __nv_bfloat16 l = __float2bfloat16(v - __bfloat162float(h));
    g_wthi[i] = h;
    g_wtlo[i] = l;
}

// ---------------- kernel 1: QKV GEMM via mma.sync bf16x3, cp.async 2-stage ----------------
#define STAGE_BYTES 40960
__global__ void __launch_bounds__(256, 2) gemm_mma(
    const float* __restrict__ bk, const float* __restrict__ bq, const float* __restrict__ bv)
{
    extern __shared__ __align__(16) unsigned char smdyn[];
    const int AHI = 0, ALO = 10240, BHI = 20480, BLO = 30720;

    int tid = threadIdx.x;
    int lane = tid & 31, wid = tid >> 5;
    int warp_m = wid >> 2;
    int warp_n = wid & 3;
    int mbase = blockIdx.y * 128;
    int nbg = blockIdx.x * 128;

    uint32_t sb = smem_to_u32(smdyn);

    float acc[4][4][4];
#pragma unroll
    for (int nt = 0; nt < 4; nt++)
#pragma unroll
        for (int mt = 0; mt < 4; mt++)
#pragma unroll
            for (int j = 0; j < 4; j++) acc[nt][mt][j] = 0.0f;

#define LOAD_CHUNK(chunk, stage) do {                                               \
        int _k0 = (chunk) * 32;                                                     \
        uint32_t _s0 = sb + (stage) * STAGE_BYTES;                                  \
        _Pragma("unroll")                                                           \
        for (int _j = 0; _j < 2; _j++) {                                            \
            int _c = tid + _j * 256;                                                \
            int _row = _c >> 2, _seg = _c & 3;                                      \
            uint32_t _so = (uint32_t)(_row * 80 + _seg * 16);                       \
            int _gn = mbase + _row;                                                 \
            int _ok = (_gn < NN);                                                   \
            const unsigned char* _pah = (const unsigned char*)(g_xhi + (size_t)(_ok ? _gn : 0) * INDIM + _k0) + _seg * 16; \
            const unsigned char* _pal = (const unsigned char*)(g_xlo + (size_t)(_ok ? _gn : 0) * INDIM + _k0) + _seg * 16; \
            cp_async16(_s0 + AHI + _so, _pah, _ok ? 16 : 0);                        \
            cp_async16(_s0 + ALO + _so, _pal, _ok ? 16 : 0);                        \
            const unsigned char* _pbh = (const unsigned char*)(g_wthi + (size_t)(nbg + _row) * INDIM + _k0) + _seg * 16; \
            const unsigned char* _pbl = (const unsigned char*)(g_wtlo + (size_t)(nbg + _row) * INDIM + _k0) + _seg * 16; \
            cp_async16(_s0 + BHI + _so, _pbh, 16);                                  \
            cp_async16(_s0 + BLO + _so, _pbl, 16);                                  \
        }                                                                           \
        asm volatile("cp.async.commit_group;" ::: "memory");                        \
    } while (0)

    LOAD_CHUNK(0, 0);

    for (int chunk = 0; chunk < 8; chunk++) {
        if (chunk + 1 < 8) {
            LOAD_CHUNK(chunk + 1, (chunk + 1) & 1);
            asm volatile("cp.async.wait_group 1;" ::: "memory");
        } else {
            asm volatile("cp.async.wait_group 0;" ::: "memory");
        }
        __syncthreads();

        uint32_t s0 = sb + (chunk & 1) * STAGE_BYTES;
#pragma unroll
        for (int ks = 0; ks < 2; ks++) {
            uint32_t bh[2][4], bl[2][4];
            int boff = ks * 32 + ((lane >> 3) & 1) * 16;
#pragma unroll
            for (int np = 0; np < 2; np++) {
                int br = warp_n * 32 + np * 16 + ((lane >> 4) & 1) * 8 + (lane & 7);
                uint32_t baddr = s0 + BHI + (uint32_t)(br * 80) + boff;
                ldsm_x4(bh[np], baddr);
                ldsm_x4(bl[np], baddr + (BLO - BHI));
            }
            int aoff = ks * 32 + ((lane >> 4) & 1) * 16;
#pragma unroll
            for (int mt = 0; mt < 4; mt++) {
                uint32_t ah[4], al[4];
                uint32_t addr = s0 + AHI + (uint32_t)((warp_m * 64 + mt * 16 + (lane & 15)) * 80) + aoff;
                ldsm_x4(ah, addr);
                ldsm_x4(al, addr + (ALO - AHI));
#pragma unroll
                for (int np = 0; np < 2; np++)
#pragma unroll
                    for (int sub = 0; sub < 2; sub++) {
                        int nt = np * 2 + sub;
                        mma_bf16(acc[nt][mt], ah, &bh[np][sub * 2]);
                        mma_bf16(acc[nt][mt], ah, &bl[np][sub * 2]);
                        mma_bf16(acc[nt][mt], al, &bh[np][sub * 2]);
                    }
            }
        }
        __syncthreads();
    }

    // epilogue: fp16 stores + bias
    int buf = nbg >> 8;
    int col0 = (nbg & 255) + warp_n * 32;
    __half* outp = (buf == 0) ? g_Kh : ((buf == 1) ? g_Qh : g_Vh);
    const float* bias = (buf == 0) ? bk : ((buf == 1) ? bq : bv);

#pragma unroll
    for (int mt = 0; mt < 4; mt++) {
        int r0 = mbase + warp_m * 64 + mt * 16 + (lane >> 2);
#pragma unroll
        for (int nt = 0; nt < 4; nt++) {
            int c = col0 + nt * 8 + (lane & 3) * 2;
            float2 bb = *(const float2*)&bias[c];
            if (r0 < NN) {
                __half2 o = __floats2half2_rn(acc[nt][mt][0] + bb.x, acc[nt][mt][1] + bb.y);
                *(__half2*)&outp[(size_t)r0 * OUTD + c] = o;
            }
            if (r0 + 8 < NN) {
                __half2 o = __floats2half2_rn(acc[nt][mt][2] + bb.x, acc[nt][mt][3] + bb.y);
                *(__half2*)&outp[(size_t)(r0 + 8) * OUTD + c] = o;
            }
        }
    }
}

// ---------------- kernel 2: node-level relation transforms (fp16 in/out) ----------------
__global__ void __launch_bounds__(288) transform_kernel(
    const float* __restrict__ msg, const float* __restrict__ msg_cau,
    const float* __restrict__ cau_filter, const float* __restrict__ time_emb,
    const int* __restrict__ cau_type)
{
    __shared__ float k_s[32][32];
    __shared__ float v_s[32][32];
    __shared__ float vt_s[32][32];
    __shared__ int ct_s[32];

    int h = blockIdx.y;
    int nodeBase = blockIdx.x * 32;
    int tid = threadIdx.x;

    for (int idx = tid; idx < 32 * 32; idx += 288) {
        int n = idx >> 5, dcol = idx & 31;
        int gn = nodeBase + n;
        float kv = 0.f, vv = 0.f;
        if (gn < NN) {
            kv = __half2float(g_Kh[(size_t)gn * OUTD + h * 32 + dcol]);
            vv = __half2float(g_Vh[(size_t)gn * OUTD + h * 32 + dcol]);
        }
        k_s[n][dcol] = kv;
        v_s[n][dcol] = vv;
        vt_s[n][dcol] = vv + time_emb[h * 32 + dcol];
    }
    for (int idx = tid; idx < 32; idx += 288) {
        int gn = nodeBase + idx;
        ct_s[idx] = (gn < NN) ? cau_type[gn] : -1;
    }
    __syncthreads();

    int wid = tid >> 5, lane = tid & 31;
    const float* mat;
    const float (*srcm)[32];
    __half* outp;
    size_t ostride;
    int myct = -1;
    if (wid < 3) {
        mat = cau_filter + (wid * NH + h) * 1024;
        srcm = k_s; outp = g_MKh; ostride = OUTD; myct = wid;
    } else if (wid < 6) {
        int e = wid - 3;
        mat = msg + (e * NH + h) * 1024;
        srcm = v_s; outp = g_VC + (size_t)e * NN * 512; ostride = 512;
    } else {
        int e = wid - 6;
        mat = msg_cau + (e * NH + h) * 1024;
        srcm = vt_s; outp = g_VC + (size_t)e * NN * 512 + 256; ostride = 512;
    }

    ull m2[16];
#pragma unroll
    for (int i = 0; i < 16; i++)
        m2[i] = pack2(mat[(2 * i) * 32 + lane], mat[(2 * i + 1) * 32 + lane]);

    for (int n = 0; n < 32; n++) {
        int gn = nodeBase + n;
        if (gn >= NN) break;
        if (myct >= 0 && ct_s[n] != myct) continue;
        ull acc = 0ull;
        const ull* row = (const ull*)&srcm[n][0];
#pragma unroll
        for (int i = 0; i < 16; i++)
            fma2(acc, row[i], m2[i]);
        float2 f = unpack2(acc);
        outp[(size_t)gn * ostride + h * 32 + lane] = __float2half(f.x + f.y);
    }
}

// ---------------- kernel 3: edge logits (fp16 rows, 1 LDG.128 per row) ----------------
// lane l owns 8 contiguous halves (dims 8l..8l+8, all within head l>>2).
// Reduce over 4-lane groups; all 8 heads in one pass.
__global__ void __launch_bounds__(256) logits_kernel(
    const int* __restrict__ src, const int* __restrict__ dst,
    const float* __restrict__ pri, const float* __restrict__ pri_cau)
{
    int e = blockIdx.y;
    int edge = blockIdx.x * 8 + (threadIdx.x >> 5);
    if (edge >= EE) return;
    int lane = threadIdx.x & 31;
    int s = src[e * EE + edge];
    int d = dst[e * EE + edge];

    uint4 qv = *(const uint4*)(g_Qh + (size_t)d * OUTD + lane * 8);
    uint4 kv = *(const uint4*)(g_Kh + (size_t)s * OUTD + lane * 8);
    uint4 mv = *(const uint4*)(g_MKh + (size_t)s * OUTD + lane * 8);

    float p = dot8h(qv, kv);
    float m = dot8h(qv, mv);
    p += __shfl_xor_sync(0xffffffffu, p, 1);
    m += __shfl_xor_sync(0xffffffffu, m, 1);
    p += __shfl_xor_sync(0xffffffffu, p, 2);
    m += __shfl_xor_sync(0xffffffffu, m, 2);

    int g = lane >> 2;
    const float isdk = 0.17677669529663687f;  // 1/sqrt(32)
    float ea = __expf(p * pri[e * NH + g] * isdk);
    float ec = __expf(m * pri_cau[e * NH + g] * isdk);

    if ((lane & 3) == 0) {
        // lanes 0,4,..,28 hold heads 0..7 -> contiguous float2 stores (64B row)
        int eidx = e * EE + edge;
        g_E[eidx * NH + g] = make_float2(ea, ec);
        red_add_v2(&g_S[(e * NN + d) * NH + g], ea, ec);
    }
}

// ---------------- kernel 4: weighted aggregation (fp16 rows, LDG.128) ----------------
__global__ void __launch_bounds__(256) aggregate_kernel(
    const int* __restrict__ src, const int* __restrict__ dst,
    const float* __restrict__ comb_pri, float* __restrict__ out)
{
    int e = blockIdx.y;
    int edge = blockIdx.x * 8 + (threadIdx.x >> 5);
    if (edge >= EE) return;
    int lane = threadIdx.x & 31;
    int s = src[e * EE + edge];
    int d = dst[e * EE + edge];
    int h = lane >> 2;
    int eidx = e * EE + edge;

    float2 eh = g_E[eidx * NH + h];
    float2 S = g_S[(e * NN + d) * NH + h];
    float wa = __fdividef(eh.x, S.x);
    float wc = __fdividef(eh.y, S.y);

    const __half* vp = g_VC + ((size_t)e * NN + s) * 512;
    float v[8], c[8];
    h8_to_f8(*(const uint4*)(vp + lane * 8), v);
    h8_to_f8(*(const uint4*)(vp + 256 + lane * 8), c);
    float4 b0 = *(const float4*)&comb_pri[e * OUTD + lane * 8];
    float4 b1 = *(const float4*)&comb_pri[e * OUTD + lane * 8 + 4];

    float r0 = wa * v[0] + wc * b0.x * c[0];
    float r1 = wa * v[1] + wc * b0.y * c[1];
    float r2 = wa * v[2] + wc * b0.z * c[2];
    float r3 = wa * v[3] + wc * b0.w * c[3];
    float r4 = wa * v[4] + wc * b1.x * c[4];
    float r5 = wa * v[5] + wc * b1.y * c[5];
    float r6 = wa * v[6] + wc * b1.z * c[6];
    float r7 = wa * v[7] + wc * b1.w * c[7];

    float* op = out + (size_t)d * OUTD + lane * 8;
    red_add_v4(op, r0, r1, r2, r3);
    red_add_v4(op + 4, r4, r5, r6, r7);
}

// ---------------- kernel 5: finalize (mean over 3 etypes + relu) ----------------
__global__ void finalize_kernel(float* __restrict__ out) {
    int i = blockIdx.x * blockDim.x + threadIdx.x;
    if (i < NN * OUTD) {
        float v = out[i] * (1.0f / 3.0f);
        out[i] = v > 0.0f ? v : 0.0f;
    }
}

// ---------------- launch ----------------
extern "C" void kernel_launch(void* const* d_in, const int* in_sizes, int n_in,
                              void* d_out, int out_size) {
    const float* x          = (const float*)d_in[0];
    const float* Wk         = (const float*)d_in[1];
    const float* bk         = (const float*)d_in[2];
    const float* Wq         = (const float*)d_in[3];
    const float* bq         = (const float*)d_in[4];
    const float* Wv         = (const float*)d_in[5];
    const float* bv         = (const float*)d_in[6];
    const float* pri        = (const float*)d_in[7];
    const float* msg        = (const float*)d_in[8];
    const float* pri_cau    = (const float*)d_in[9];
    const float* msg_cau    = (const float*)d_in[10];
    const float* comb_pri   = (const float*)d_in[11];
    const float* cau_filter = (const float*)d_in[12];
    const float* time_emb   = (const float*)d_in[13];
    const int*   cau_type   = (const int*)d_in[14];
    const int*   src        = (const int*)d_in[15];
    const int*   dst        = (const int*)d_in[16];
    float* out = (float*)d_out;

    zero_kernel<<<2048, 256>>>(out);

    split_x_kernel<<<(NN * INDIM / 4 + 255) / 256, 256>>>(x);
    split_w_kernel<<<768, 256>>>(Wk, Wq, Wv);

    cudaFuncSetAttribute(gemm_mma, cudaFuncAttributeMaxDynamicSharedMemorySize,
                         2 * STAGE_BYTES);
    gemm_mma<<<dim3(6, 157), 256, 2 * STAGE_BYTES>>>(bk, bq, bv);

    dim3 tgrid((NN + 31) / 32, NH);
    transform_kernel<<<tgrid, 288>>>(msg, msg_cau, cau_filter, time_emb, cau_type);

    dim3 egrid((EE + 7) / 8, 3);
    logits_kernel<<<egrid, 256>>>(src, dst, pri, pri_cau);
    aggregate_kernel<<<egrid, 256>>>(src, dst, comb_pri, out);

    finalize_kernel<<<(NN * OUTD + 255) / 256, 256>>>(out);
}

// round 12
// speedup vs baseline: 1.0642x; 1.0642x over previous
#include <cuda_runtime.h>
#include <cuda_bf16.h>
#include <cuda_fp16.h>
#include <math.h>
#include <stdint.h>

#define NN 20000
#define EE 160000
#define OUTD 256
#define INDIM 256
#define NH 8

typedef unsigned long long ull;

// ---------------- scratch (device globals; no allocation allowed) ----------------
__device__ float g_K[NN * OUTD];
__device__ float g_Q[NN * OUTD];
__device__ float g_V[NN * OUTD];
__device__ float g_MK[NN * OUTD];
__device__ __half g_VC[(size_t)3 * NN * 512];  // per (etype,node): [0,256)=val fp16, [256,512)=cval fp16
__device__ float2 g_E[3 * EE * NH];      // (ea, eca) per edge-head
__device__ float2 g_S[3 * NN * NH];      // (sum_ea, sum_eca) per dst-head
// bf16 hi/lo splits for tensor-core GEMM
__device__ __nv_bfloat16 g_xhi[NN * INDIM];
__device__ __nv_bfloat16 g_xlo[NN * INDIM];
__device__ __nv_bfloat16 g_wthi[768 * INDIM];   // [out_col][k] transposed
__device__ __nv_bfloat16 g_wtlo[768 * INDIM];

// ---------------- helpers ----------------
__device__ __forceinline__ ull pack2(float a, float b) {
    ull r; asm("mov.b64 %0, {%1, %2};" : "=l"(r) : "f"(a), "f"(b)); return r;
}
__device__ __forceinline__ void fma2(ull& acc, ull a, ull b) {
    asm("fma.rn.f32x2 %0, %1, %2, %0;" : "+l"(acc) : "l"(a), "l"(b));
}
__device__ __forceinline__ float2 unpack2(ull v) {
    float2 f; asm("mov.b64 {%0, %1}, %2;" : "=f"(f.x), "=f"(f.y) : "l"(v)); return f;
}
__device__ __forceinline__ float dot4(float4 a, float4 b) {
    return a.x * b.x + a.y * b.y + a.z * b.z + a.w * b.w;
}
__device__ __forceinline__ void red_add_v4(float* p, float a, float b, float c, float d) {
    asm volatile("red.global.add.v4.f32 [%0], {%1,%2,%3,%4};"
                 :: "l"(p), "f"(a), "f"(b), "f"(c), "f"(d) : "memory");
}
__device__ __forceinline__ void red_add_v2(float2* p, float a, float b) {
    asm volatile("red.global.add.v2.f32 [%0], {%1,%2};"
                 :: "l"(p), "f"(a), "f"(b) : "memory");
}
__device__ __forceinline__ uint32_t smem_to_u32(const void* p) {
    uint32_t a;
    asm("{ .reg .u64 t; cvta.to.shared.u64 t, %1; cvt.u32.u64 %0, t; }" : "=r"(a) : "l"(p));
    return a;
}
__device__ __forceinline__ void ldsm_x4(uint32_t* r, uint32_t addr) {
    asm volatile("ldmatrix.sync.aligned.m8n8.x4.shared.b16 {%0,%1,%2,%3}, [%4];"
        : "=r"(r[0]), "=r"(r[1]), "=r"(r[2]), "=r"(r[3]) : "r"(addr));
}
__device__ __forceinline__ void mma_bf16(float* c, const uint32_t* a, const uint32_t* b) {
    asm volatile("mma.sync.aligned.m16n8k16.row.col.f32.bf16.bf16.f32 "
        "{%0,%1,%2,%3}, {%4,%5,%6,%7}, {%8,%9}, {%0,%1,%2,%3};"
        : "+f"(c[0]), "+f"(c[1]), "+f"(c[2]), "+f"(c[3])
        : "r"(a[0]), "r"(a[1]), "r"(a[2]), "r"(a[3]), "r"(b[0]), "r"(b[1]));
}
__device__ __forceinline__ void cp_async16(uint32_t dst, const void* src, int sz) {
    asm volatile("cp.async.ca.shared.global [%0], [%1], 16, %2;"
                 :: "r"(dst), "l"(src), "r"(sz) : "memory");
}
__device__ __forceinline__ float4 h4_to_f4(uint2 u) {
    __half2 a = *(__half2*)&u.x, b = *(__half2*)&u.y;
    float2 fa = __half22float2(a), fb = __half22float2(b);
    return make_float4(fa.x, fa.y, fb.x, fb.y);
}

// ---------------- kernel 0: zero accumulators ----------------
__global__ void zero_kernel(float* __restrict__ out) {
    int stride = gridDim.x * blockDim.x;
    for (int i = blockIdx.x * blockDim.x + threadIdx.x; i < NN * OUTD; i += stride)
        out[i] = 0.0f;
    float2 z2 = make_float2(0.f, 0.f);
    for (int i = blockIdx.x * blockDim.x + threadIdx.x; i < 3 * NN * NH; i += stride)
        g_S[i] = z2;
}

// ---------------- prep: fp32 -> bf16 hi/lo splits ----------------
__global__ void split_x_kernel(const float* __restrict__ x) {
    int i = blockIdx.x * blockDim.x + threadIdx.x;
    if (i >= NN * INDIM / 4) return;
    float4 v = ((const float4*)x)[i];
    __nv_bfloat16 h[4], l[4];
    float f[4] = {v.x, v.y, v.z, v.w};
#pragma unroll
    for (int j = 0; j < 4; j++) {
        h[j] = __float2bfloat16(f[j]);
        l[j] = __float2bfloat16(f[j] - __bfloat162float(h[j]));
    }
    ((uint2*)g_xhi)[i] = *(uint2*)h;
    ((uint2*)g_xlo)[i] = *(uint2*)l;
}

__global__ void split_w_kernel(const float* __restrict__ Wk,
                               const float* __restrict__ Wq,
                               const float* __restrict__ Wv) {
    int i = blockIdx.x * blockDim.x + threadIdx.x;   // i = c*256 + k
    if (i >= 768 * INDIM) return;
    int c = i >> 8, k = i & 255;
    const float* W = (c < 256) ? Wk : ((c < 512) ? Wq : Wv);
    float v = W[k * 256 + (c & 255)];
    __nv_bfloat16 h = __float2bfloat16(v);
    __nv_bfloat16 l = __float2bfloat16(v - __bfloat162float(h));
    g_wthi[i] = h;
    g_wtlo[i] = l;
}

// ---------------- kernel 1: QKV GEMM via mma.sync bf16x3, cp.async 2-stage ----------------
#define STAGE_BYTES 40960
__global__ void __launch_bounds__(256, 2) gemm_mma(
    const float* __restrict__ bk, const float* __restrict__ bq, const float* __restrict__ bv)
{
    extern __shared__ __align__(16) unsigned char smdyn[];
    const int AHI = 0, ALO = 10240, BHI = 20480, BLO = 30720;

    int tid = threadIdx.x;
    int lane = tid & 31, wid = tid >> 5;
    int warp_m = wid >> 2;
    int warp_n = wid & 3;
    int mbase = blockIdx.y * 128;
    int nbg = blockIdx.x * 128;

    uint32_t sb = smem_to_u32(smdyn);

    float acc[4][4][4];
#pragma unroll
    for (int nt = 0; nt < 4; nt++)
#pragma unroll
        for (int mt = 0; mt < 4; mt++)
#pragma unroll
            for (int j = 0; j < 4; j++) acc[nt][mt][j] = 0.0f;

#define LOAD_CHUNK(chunk, stage) do {                                               \
        int _k0 = (chunk) * 32;                                                     \
        uint32_t _s0 = sb + (stage) * STAGE_BYTES;                                  \
        _Pragma("unroll")                                                           \
        for (int _j = 0; _j < 2; _j++) {                                            \
            int _c = tid + _j * 256;                                                \
            int _row = _c >> 2, _seg = _c & 3;                                      \
            uint32_t _so = (uint32_t)(_row * 80 + _seg * 16);                       \
            int _gn = mbase + _row;                                                 \
            int _ok = (_gn < NN);                                                   \
            const unsigned char* _pah = (const unsigned char*)(g_xhi + (size_t)(_ok ? _gn : 0) * INDIM + _k0) + _seg * 16; \
            const unsigned char* _pal = (const unsigned char*)(g_xlo + (size_t)(_ok ? _gn : 0) * INDIM + _k0) + _seg * 16; \
            cp_async16(_s0 + AHI + _so, _pah, _ok ? 16 : 0);                        \
            cp_async16(_s0 + ALO + _so, _pal, _ok ? 16 : 0);                        \
            const unsigned char* _pbh = (const unsigned char*)(g_wthi + (size_t)(nbg + _row) * INDIM + _k0) + _seg * 16; \
            const unsigned char* _pbl = (const unsigned char*)(g_wtlo + (size_t)(nbg + _row) * INDIM + _k0) + _seg * 16; \
            cp_async16(_s0 + BHI + _so, _pbh, 16);                                  \
            cp_async16(_s0 + BLO + _so, _pbl, 16);                                  \
        }                                                                           \
        asm volatile("cp.async.commit_group;" ::: "memory");                        \
    } while (0)

    LOAD_CHUNK(0, 0);

    for (int chunk = 0; chunk < 8; chunk++) {
        if (chunk + 1 < 8) {
            LOAD_CHUNK(chunk + 1, (chunk + 1) & 1);
            asm volatile("cp.async.wait_group 1;" ::: "memory");
        } else {
            asm volatile("cp.async.wait_group 0;" ::: "memory");
        }
        __syncthreads();

        uint32_t s0 = sb + (chunk & 1) * STAGE_BYTES;
#pragma unroll
        for (int ks = 0; ks < 2; ks++) {
            uint32_t bh[2][4], bl[2][4];
            int boff = ks * 32 + ((lane >> 3) & 1) * 16;
#pragma unroll
            for (int np = 0; np < 2; np++) {
                int br = warp_n * 32 + np * 16 + ((lane >> 4) & 1) * 8 + (lane & 7);
                uint32_t baddr = s0 + BHI + (uint32_t)(br * 80) + boff;
                ldsm_x4(bh[np], baddr);
                ldsm_x4(bl[np], baddr + (BLO - BHI));
            }
            int aoff = ks * 32 + ((lane >> 4) & 1) * 16;
#pragma unroll
            for (int mt = 0; mt < 4; mt++) {
                uint32_t ah[4], al[4];
                uint32_t addr = s0 + AHI + (uint32_t)((warp_m * 64 + mt * 16 + (lane & 15)) * 80) + aoff;
                ldsm_x4(ah, addr);
                ldsm_x4(al, addr + (ALO - AHI));
#pragma unroll
                for (int np = 0; np < 2; np++)
#pragma unroll
                    for (int sub = 0; sub < 2; sub++) {
                        int nt = np * 2 + sub;
                        mma_bf16(acc[nt][mt], ah, &bh[np][sub * 2]);
                        mma_bf16(acc[nt][mt], ah, &bl[np][sub * 2]);
                        mma_bf16(acc[nt][mt], al, &bh[np][sub * 2]);
                    }
            }
        }
        __syncthreads();
    }

    // epilogue: direct float2 stores + bias
    int buf = nbg >> 8;
    int col0 = (nbg & 255) + warp_n * 32;
    float* outp = (buf == 0) ? g_K : ((buf == 1) ? g_Q : g_V);
    const float* bias = (buf == 0) ? bk : ((buf == 1) ? bq : bv);

#pragma unroll
    for (int mt = 0; mt < 4; mt++) {
        int r0 = mbase + warp_m * 64 + mt * 16 + (lane >> 2);
#pragma unroll
        for (int nt = 0; nt < 4; nt++) {
            int c = col0 + nt * 8 + (lane & 3) * 2;
            float2 bb = *(const float2*)&bias[c];
            if (r0 < NN) {
                float2 o = make_float2(acc[nt][mt][0] + bb.x, acc[nt][mt][1] + bb.y);
                *(float2*)&outp[(size_t)r0 * OUTD + c] = o;
            }
            if (r0 + 8 < NN) {
                float2 o = make_float2(acc[nt][mt][2] + bb.x, acc[nt][mt][3] + bb.y);
                *(float2*)&outp[(size_t)(r0 + 8) * OUTD + c] = o;
            }
        }
    }
}

// ---------------- kernel 2: node-level relation transforms ----------------
// MK stays fp32 (feeds logits); val/cval stored fp16 into g_VC.
__global__ void __launch_bounds__(288) transform_kernel(
    const float* __restrict__ msg, const float* __restrict__ msg_cau,
    const float* __restrict__ cau_filter, const float* __restrict__ time_emb,
    const int* __restrict__ cau_type)
{
    __shared__ float k_s[32][32];
    __shared__ float v_s[32][32];
    __shared__ float vt_s[32][32];
    __shared__ int ct_s[32];

    int h = blockIdx.y;
    int nodeBase = blockIdx.x * 32;
    int tid = threadIdx.x;

    for (int idx = tid; idx < 32 * 32; idx += 288) {
        int n = idx >> 5, dcol = idx & 31;
        int gn = nodeBase + n;
        float kv = 0.f, vv = 0.f;
        if (gn < NN) {
            kv = g_K[gn * OUTD + h * 32 + dcol];
            vv = g_V[gn * OUTD + h * 32 + dcol];
        }
        k_s[n][dcol] = kv;
        v_s[n][dcol] = vv;
        vt_s[n][dcol] = vv + time_emb[h * 32 + dcol];
    }
    for (int idx = tid; idx < 32; idx += 288) {
        int gn = nodeBase + idx;
        ct_s[idx] = (gn < NN) ? cau_type[gn] : -1;
    }
    __syncthreads();

    int wid = tid >> 5, lane = tid & 31;
    const float* mat;
    const float (*srcm)[32];
    float* outp_f = 0;
    __half* outp_h = 0;
    int myct = -1;
    if (wid < 3) {
        mat = cau_filter + (wid * NH + h) * 1024;
        srcm = k_s; outp_f = g_MK; myct = wid;
    } else if (wid < 6) {
        int e = wid - 3;
        mat = msg + (e * NH + h) * 1024;
        srcm = v_s; outp_h = g_VC + (size_t)e * NN * 512;      // val at offset 0
    } else {
        int e = wid - 6;
        mat = msg_cau + (e * NH + h) * 1024;
        srcm = vt_s; outp_h = g_VC + (size_t)e * NN * 512 + 256;  // cval at +256
    }

    ull m2[16];
#pragma unroll
    for (int i = 0; i < 16; i++)
        m2[i] = pack2(mat[(2 * i) * 32 + lane], mat[(2 * i + 1) * 32 + lane]);

    for (int n = 0; n < 32; n++) {
        int gn = nodeBase + n;
        if (gn >= NN) break;
        if (myct >= 0 && ct_s[n] != myct) continue;
        ull acc = 0ull;
        const ull* row = (const ull*)&srcm[n][0];
#pragma unroll
        for (int i = 0; i < 16; i++)
            fma2(acc, row[i], m2[i]);
        float2 f = unpack2(acc);
        float r = f.x + f.y;
        if (outp_f) outp_f[gn * OUTD + h * 32 + lane] = r;
        else        outp_h[(size_t)gn * 512 + h * 32 + lane] = __float2half(r);
    }
}

// ---------------- kernel 3: edge logits + softmax denominators ----------------
// Parity-packed butterfly: 6 reduce shuffles (was 12) and 2 exps (was 4).
__global__ void __launch_bounds__(256) logits_kernel(
    const int* __restrict__ src, const int* __restrict__ dst,
    const float* __restrict__ pri, const float* __restrict__ pri_cau)
{
    int e = blockIdx.y;
    int edge = blockIdx.x * 8 + (threadIdx.x >> 5);
    if (edge >= EE) return;
    int lane = threadIdx.x & 31;
    int s = src[e * EE + edge];
    int d = dst[e * EE + edge];
    int off = lane * 4;

    const float* qp = g_Q + d * OUTD;
    const float* kp = g_K + s * OUTD;
    const float* mp = g_MK + s * OUTD;
    float4 qa = *(const float4*)(qp + off);
    float4 qb = *(const float4*)(qp + 128 + off);
    float4 ka = *(const float4*)(kp + off);
    float4 kb = *(const float4*)(kp + 128 + off);
    float4 ma = *(const float4*)(mp + off);
    float4 mb = *(const float4*)(mp + 128 + off);

    // partial dots: p0 -> head (lane>>3), p1 -> head (lane>>3)+4
    float p0 = dot4(qa, ka);
    float p1 = dot4(qb, kb);
    float m0 = dot4(qa, ma);
    float m1 = dot4(qb, mb);

    // parity pack: even lanes accumulate head g (p0/m0), odd lanes head g+4 (p1/m1)
    int odd = lane & 1;
    float pv = odd ? p0 : p1;                     // value sent to partner
    float mv = odd ? m0 : m1;
    float pr = __shfl_xor_sync(0xffffffffu, pv, 1);
    float mr = __shfl_xor_sync(0xffffffffu, mv, 1);
    float P = (odd ? p1 : p0) + pr;               // pair-reduced, parity-specialized
    float M = (odd ? m1 : m0) + mr;
    P += __shfl_xor_sync(0xffffffffu, P, 2);
    M += __shfl_xor_sync(0xffffffffu, M, 2);
    P += __shfl_xor_sync(0xffffffffu, P, 4);
    M += __shfl_xor_sync(0xffffffffu, M, 4);

    // this lane's head: g = lane>>3 (even) or lane>>3 + 4 (odd)
    int hh = (lane >> 3) + (odd << 2);
    const float isdk = 0.17677669529663687f;  // 1/sqrt(32)
    float ea = __expf(P * pri[e * NH + hh] * isdk);
    float ec = __expf(M * pri_cau[e * NH + hh] * isdk);

    // redistribute: lane h (0..7) takes head h from lane (h&3)*8 + (h>>2)
    int srcl = (lane & 3) * 8 + ((lane >> 2) & 1);
    float va = __shfl_sync(0xffffffffu, ea, srcl);
    float vc = __shfl_sync(0xffffffffu, ec, srcl);

    if (lane < NH) {
        int eidx = e * EE + edge;
        g_E[eidx * NH + lane] = make_float2(va, vc);
        red_add_v2(&g_S[(e * NN + d) * NH + lane], va, vc);
    }
}

// ---------------- kernel 4: weighted aggregation (fp16 VC gathers) ----------------
__global__ void __launch_bounds__(256) aggregate_kernel(
    const int* __restrict__ src, const int* __restrict__ dst,
    const float* __restrict__ comb_pri, float* __restrict__ out)
{
    int e = blockIdx.y;
    int edge = blockIdx.x * 8 + (threadIdx.x >> 5);
    if (edge >= EE) return;
    int lane = threadIdx.x & 31;
    int s = src[e * EE + edge];
    int d = dst[e * EE + edge];
    int h0 = lane >> 3;
    int h1 = h0 + 4;
    int eidx = e * EE + edge;

    float2 eh0 = g_E[eidx * NH + h0];
    float2 eh1 = g_E[eidx * NH + h1];
    float2 s0 = g_S[(e * NN + d) * NH + h0];
    float2 s1 = g_S[(e * NN + d) * NH + h1];
    float wa0 = __fdividef(eh0.x, s0.x);
    float wc0 = __fdividef(eh0.y, s0.y);
    float wa1 = __fdividef(eh1.x, s1.x);
    float wc1 = __fdividef(eh1.y, s1.y);

    int off = lane * 4;
    const __half* vp = g_VC + ((size_t)e * NN + s) * 512;
    float4 v0 = h4_to_f4(*(const uint2*)(vp + off));
    float4 v1 = h4_to_f4(*(const uint2*)(vp + 128 + off));
    float4 c0 = h4_to_f4(*(const uint2*)(vp + 256 + off));
    float4 c1 = h4_to_f4(*(const uint2*)(vp + 384 + off));
    float4 b0 = *(const float4*)&comb_pri[e * OUTD + off];
    float4 b1 = *(const float4*)&comb_pri[e * OUTD + 128 + off];

    float r0 = wa0 * v0.x + wc0 * b0.x * c0.x;
    float r1 = wa0 * v0.y + wc0 * b0.y * c0.y;
    float r2 = wa0 * v0.z + wc0 * b0.z * c0.z;
    float r3 = wa0 * v0.w + wc0 * b0.w * c0.w;
    float r4 = wa1 * v1.x + wc1 * b1.x * c1.x;
    float r5 = wa1 * v1.y + wc1 * b1.y * c1.y;
    float r6 = wa1 * v1.z + wc1 * b1.z * c1.z;
    float r7 = wa1 * v1.w + wc1 * b1.w * c1.w;

    float* op = out + d * OUTD;
    red_add_v4(op + off, r0, r1, r2, r3);
    red_add_v4(op + 128 + off, r4, r5, r6, r7);
}

// ---------------- kernel 5: finalize (mean over 3 etypes + relu) ----------------
__global__ void finalize_kernel(float* __restrict__ out) {
    int i = blockIdx.x * blockDim.x + threadIdx.x;
    if (i < NN * OUTD) {
        float v = out[i] * (1.0f / 3.0f);
        out[i] = v > 0.0f ? v : 0.0f;
    }
}

// ---------------- launch ----------------
extern "C" void kernel_launch(void* const* d_in, const int* in_sizes, int n_in,
                              void* d_out, int out_size) {
    const float* x          = (const float*)d_in[0];
    const float* Wk         = (const float*)d_in[1];
    const float* bk         = (const float*)d_in[2];
    const float* Wq         = (const float*)d_in[3];
    const float* bq         = (const float*)d_in[4];
    const float* Wv         = (const float*)d_in[5];
    const float* bv         = (const float*)d_in[6];
    const float* pri        = (const float*)d_in[7];
    const float* msg        = (const float*)d_in[8];
    const float* pri_cau    = (const float*)d_in[9];
    const float* msg_cau    = (const float*)d_in[10];
    const float* comb_pri   = (const float*)d_in[11];
    const float* cau_filter = (const float*)d_in[12];
    const float* time_emb   = (const float*)d_in[13];
    const int*   cau_type   = (const int*)d_in[14];
    const int*   src        = (const int*)d_in[15];
    const int*   dst        = (const int*)d_in[16];
    float* out = (float*)d_out;

    zero_kernel<<<2048, 256>>>(out);

    split_x_kernel<<<(NN * INDIM / 4 + 255) / 256, 256>>>(x);
    split_w_kernel<<<768, 256>>>(Wk, Wq, Wv);

    cudaFuncSetAttribute(gemm_mma, cudaFuncAttributeMaxDynamicSharedMemorySize,
                         2 * STAGE_BYTES);
    gemm_mma<<<dim3(6, 157), 256, 2 * STAGE_BYTES>>>(bk, bq, bv);

    dim3 tgrid((NN + 31) / 32, NH);
    transform_kernel<<<tgrid, 288>>>(msg, msg_cau, cau_filter, time_emb, cau_type);

    dim3 egrid((EE + 7) / 8, 3);
    logits_kernel<<<egrid, 256>>>(src, dst, pri, pri_cau);
    aggregate_kernel<<<egrid, 256>>>(src, dst, comb_pri, out);

    finalize_kernel<<<(NN * OUTD + 255) / 256, 256>>>(out);
}

// round 14
// speedup vs baseline: 1.1161x; 1.0488x over previous
#include <cuda_runtime.h>
#include <cuda_bf16.h>
#include <cuda_fp16.h>
#include <math.h>
#include <stdint.h>

#define NN 20000
#define EE 160000
#define OUTD 256
#define INDIM 256
#define NH 8

typedef unsigned long long ull;

// ---------------- scratch (device globals; no allocation allowed) ----------------
__device__ float g_K[NN * OUTD];
__device__ float g_Q[NN * OUTD];
__device__ float g_V[NN * OUTD];
__device__ __half g_KMh[(size_t)NN * 512];     // per node: [0,256)=k fp16, [256,512)=mk fp16
__device__ __half g_VC[(size_t)3 * NN * 512];  // per (etype,node): [0,256)=val, [256,512)=cval
__device__ float2 g_E[3 * EE * NH];            // (ea, eca) per edge-head
__device__ float2 g_S[3 * NN * NH];            // (sum_ea, sum_eca) per dst-head
// bf16 hi/lo splits for tensor-core GEMM
__device__ __nv_bfloat16 g_xhi[NN * INDIM];
__device__ __nv_bfloat16 g_xlo[NN * INDIM];
__device__ __nv_bfloat16 g_wthi[768 * INDIM];   // [out_col][k] transposed
__device__ __nv_bfloat16 g_wtlo[768 * INDIM];

// ---------------- helpers ----------------
__device__ __forceinline__ ull pack2(float a, float b) {
    ull r; asm("mov.b64 %0, {%1, %2};" : "=l"(r) : "f"(a), "f"(b)); return r;
}
__device__ __forceinline__ void fma2(ull& acc, ull a, ull b) {
    asm("fma.rn.f32x2 %0, %1, %2, %0;" : "+l"(acc) : "l"(a), "l"(b));
}
__device__ __forceinline__ float2 unpack2(ull v) {
    float2 f; asm("mov.b64 {%0, %1}, %2;" : "=f"(f.x), "=f"(f.y) : "l"(v)); return f;
}
__device__ __forceinline__ float dot4(float4 a, float4 b) {
    return a.x * b.x + a.y * b.y + a.z * b.z + a.w * b.w;
}
__device__ __forceinline__ void red_add_v4(float* p, float a, float b, float c, float d) {
    asm volatile("red.global.add.v4.f32 [%0], {%1,%2,%3,%4};"
                 :: "l"(p), "f"(a), "f"(b), "f"(c), "f"(d) : "memory");
}
__device__ __forceinline__ void red_add_v2(float2* p, float a, float b) {
    asm volatile("red.global.add.v2.f32 [%0], {%1,%2};"
                 :: "l"(p), "f"(a), "f"(b) : "memory");
}
__device__ __forceinline__ uint32_t smem_to_u32(const void* p) {
    uint32_t a;
    asm("{ .reg .u64 t; cvta.to.shared.u64 t, %1; cvt.u32.u64 %0, t; }" : "=r"(a) : "l"(p));
    return a;
}
__device__ __forceinline__ void ldsm_x4(uint32_t* r, uint32_t addr) {
    asm volatile("ldmatrix.sync.aligned.m8n8.x4.shared.b16 {%0,%1,%2,%3}, [%4];"
        : "=r"(r[0]), "=r"(r[1]), "=r"(r[2]), "=r"(r[3]) : "r"(addr));
}
__device__ __forceinline__ void mma_bf16(float* c, const uint32_t* a, const uint32_t* b) {
    asm volatile("mma.sync.aligned.m16n8k16.row.col.f32.bf16.bf16.f32 "
        "{%0,%1,%2,%3}, {%4,%5,%6,%7}, {%8,%9}, {%0,%1,%2,%3};"
        : "+f"(c[0]), "+f"(c[1]), "+f"(c[2]), "+f"(c[3])
        : "r"(a[0]), "r"(a[1]), "r"(a[2]), "r"(a[3]), "r"(b[0]), "r"(b[1]));
}
__device__ __forceinline__ void cp_async16(uint32_t dst, const void* src, int sz) {
    asm volatile("cp.async.ca.shared.global [%0], [%1], 16, %2;"
                 :: "r"(dst), "l"(src), "r"(sz) : "memory");
}
__device__ __forceinline__ float4 h4_to_f4(uint2 u) {
    __half2 a = *(__half2*)&u.x, b = *(__half2*)&u.y;
    float2 fa = __half22float2(a), fb = __half22float2(b);
    return make_float4(fa.x, fa.y, fb.x, fb.y);
}

// ---------------- prep: fp32 -> bf16 hi/lo splits (+ zero g_S) ----------------
__global__ void split_x_kernel(const float* __restrict__ x) {
    int i = blockIdx.x * blockDim.x + threadIdx.x;
    if (i < 3 * NN * NH) g_S[i] = make_float2(0.f, 0.f);
    if (i >= NN * INDIM / 4) return;
    float4 v = ((const float4*)x)[i];
    __nv_bfloat16 h[4], l[4];
    float f[4] = {v.x, v.y, v.z, v.w};
#pragma unroll
    for (int j = 0; j < 4; j++) {
        h[j] = __float2bfloat16(f[j]);
        l[j] = __float2bfloat16(f[j] - __bfloat162float(h[j]));
    }
    ((uint2*)g_xhi)[i] = *(uint2*)h;
    ((uint2*)g_xlo)[i] = *(uint2*)l;
}

__global__ void split_w_kernel(const float* __restrict__ Wk,
                               const float* __restrict__ Wq,
                               const float* __restrict__ Wv) {
    int i = blockIdx.x * blockDim.x + threadIdx.x;   // i = c*256 + k
    if (i >= 768 * INDIM) return;
    int c = i >> 8, k = i & 255;
    const float* W = (c < 256) ? Wk : ((c < 512) ? Wq : Wv);
    float v = W[k * 256 + (c & 255)];
    __nv_bfloat16 h = __float2bfloat16(v);
    __nv_bfloat16 l = __float2bfloat16(v - __bfloat162float(h));
    g_wthi[i] = h;
    g_wtlo[i] = l;
}

// ---------------- kernel 1: QKV GEMM via mma.sync bf16x3, cp.async 2-stage ----------------
#define STAGE_BYTES 40960
__global__ void __launch_bounds__(256, 2) gemm_mma(
    const float* __restrict__ bk, const float* __restrict__ bq, const float* __restrict__ bv)
{
    extern __shared__ __align__(16) unsigned char smdyn[];
    const int AHI = 0, ALO = 10240, BHI = 20480, BLO = 30720;

    int tid = threadIdx.x;
    int lane = tid & 31, wid = tid >> 5;
    int warp_m = wid >> 2;
    int warp_n = wid & 3;
    int mbase = blockIdx.y * 128;
    int nbg = blockIdx.x * 128;

    uint32_t sb = smem_to_u32(smdyn);

    float acc[4][4][4];
#pragma unroll
    for (int nt = 0; nt < 4; nt++)
#pragma unroll
        for (int mt = 0; mt < 4; mt++)
#pragma unroll
            for (int j = 0; j < 4; j++) acc[nt][mt][j] = 0.0f;

#define LOAD_CHUNK(chunk, stage) do {                                               \
        int _k0 = (chunk) * 32;                                                     \
        uint32_t _s0 = sb + (stage) * STAGE_BYTES;                                  \
        _Pragma("unroll")                                                           \
        for (int _j = 0; _j < 2; _j++) {                                            \
            int _c = tid + _j * 256;                                                \
            int _row = _c >> 2, _seg = _c & 3;                                      \
            uint32_t _so = (uint32_t)(_row * 80 + _seg * 16);                       \
            int _gn = mbase + _row;                                                 \
            int _ok = (_gn < NN);                                                   \
            const unsigned char* _pah = (const unsigned char*)(g_xhi + (size_t)(_ok ? _gn : 0) * INDIM + _k0) + _seg * 16; \
            const unsigned char* _pal = (const unsigned char*)(g_xlo + (size_t)(_ok ? _gn : 0) * INDIM + _k0) + _seg * 16; \
            cp_async16(_s0 + AHI + _so, _pah, _ok ? 16 : 0);                        \
            cp_async16(_s0 + ALO + _so, _pal, _ok ? 16 : 0);                        \
            const unsigned char* _pbh = (const unsigned char*)(g_wthi + (size_t)(nbg + _row) * INDIM + _k0) + _seg * 16; \
            const unsigned char* _pbl = (const unsigned char*)(g_wtlo + (size_t)(nbg + _row) * INDIM + _k0) + _seg * 16; \
            cp_async16(_s0 + BHI + _so, _pbh, 16);                                  \
            cp_async16(_s0 + BLO + _so, _pbl, 16);                                  \
        }                                                                           \
        asm volatile("cp.async.commit_group;" ::: "memory");                        \
    } while (0)

    LOAD_CHUNK(0, 0);

    for (int chunk = 0; chunk < 8; chunk++) {
        if (chunk + 1 < 8) {
            LOAD_CHUNK(chunk + 1, (chunk + 1) & 1);
            asm volatile("cp.async.wait_group 1;" ::: "memory");
        } else {
            asm volatile("cp.async.wait_group 0;" ::: "memory");
        }
        __syncthreads();

        uint32_t s0 = sb + (chunk & 1) * STAGE_BYTES;
#pragma unroll
        for (int ks = 0; ks < 2; ks++) {
            uint32_t bh[2][4], bl[2][4];
            int boff = ks * 32 + ((lane >> 3) & 1) * 16;
#pragma unroll
            for (int np = 0; np < 2; np++) {
                int br = warp_n * 32 + np * 16 + ((lane >> 4) & 1) * 8 + (lane & 7);
                uint32_t baddr = s0 + BHI + (uint32_t)(br * 80) + boff;
                ldsm_x4(bh[np], baddr);
                ldsm_x4(bl[np], baddr + (BLO - BHI));
            }
            int aoff = ks * 32 + ((lane >> 4) & 1) * 16;
#pragma unroll
            for (int mt = 0; mt < 4; mt++) {
                uint32_t ah[4], al[4];
                uint32_t addr = s0 + AHI + (uint32_t)((warp_m * 64 + mt * 16 + (lane & 15)) * 80) + aoff;
                ldsm_x4(ah, addr);
                ldsm_x4(al, addr + (ALO - AHI));
#pragma unroll
                for (int np = 0; np < 2; np++)
#pragma unroll
                    for (int sub = 0; sub < 2; sub++) {
                        int nt = np * 2 + sub;
                        mma_bf16(acc[nt][mt], ah, &bh[np][sub * 2]);
                        mma_bf16(acc[nt][mt], ah, &bl[np][sub * 2]);
                        mma_bf16(acc[nt][mt], al, &bh[np][sub * 2]);
                    }
            }
        }
        __syncthreads();
    }

    // epilogue: fp32 stores + bias; K additionally mirrored to fp16 g_KMh[:, 0..256)
    int buf = nbg >> 8;
    int col0 = (nbg & 255) + warp_n * 32;
    float* outp = (buf == 0) ? g_K : ((buf == 1) ? g_Q : g_V);
    const float* bias = (buf == 0) ? bk : ((buf == 1) ? bq : bv);
    bool isK = (buf == 0);

#pragma unroll
    for (int mt = 0; mt < 4; mt++) {
        int r0 = mbase + warp_m * 64 + mt * 16 + (lane >> 2);
#pragma unroll
        for (int nt = 0; nt < 4; nt++) {
            int c = col0 + nt * 8 + (lane & 3) * 2;
            float2 bb = *(const float2*)&bias[c];
            if (r0 < NN) {
                float2 o = make_float2(acc[nt][mt][0] + bb.x, acc[nt][mt][1] + bb.y);
                *(float2*)&outp[(size_t)r0 * OUTD + c] = o;
                if (isK)
                    *(__half2*)&g_KMh[(size_t)r0 * 512 + c] = __floats2half2_rn(o.x, o.y);
            }
            if (r0 + 8 < NN) {
                float2 o = make_float2(acc[nt][mt][2] + bb.x, acc[nt][mt][3] + bb.y);
                *(float2*)&outp[(size_t)(r0 + 8) * OUTD + c] = o;
                if (isK)
                    *(__half2*)&g_KMh[(size_t)(r0 + 8) * 512 + c] = __floats2half2_rn(o.x, o.y);
            }
        }
    }
}

// ---------------- kernel 2: node-level relation transforms (+ zero out) ----------------
// MK -> fp16 g_KMh[:, 256..512); val/cval -> fp16 g_VC.
__global__ void __launch_bounds__(288) transform_kernel(
    const float* __restrict__ msg, const float* __restrict__ msg_cau,
    const float* __restrict__ cau_filter, const float* __restrict__ time_emb,
    const int* __restrict__ cau_type, float* __restrict__ out)
{
    __shared__ float k_s[32][32];
    __shared__ float v_s[32][32];
    __shared__ float vt_s[32][32];
    __shared__ int ct_s[32];

    int h = blockIdx.y;
    int nodeBase = blockIdx.x * 32;
    int tid = threadIdx.x;

    // fold output zeroing in (completes before aggregate launches)
    {
        int bid = blockIdx.y * gridDim.x + blockIdx.x;
        int gtid = bid * 288 + tid;
        int nthreads = gridDim.x * gridDim.y * 288;
        for (int i = gtid; i < NN * OUTD / 4; i += nthreads)
            ((float4*)out)[i] = make_float4(0.f, 0.f, 0.f, 0.f);
    }

    for (int idx = tid; idx < 32 * 32; idx += 288) {
        int n = idx >> 5, dcol = idx & 31;
        int gn = nodeBase + n;
        float kv = 0.f, vv = 0.f;
        if (gn < NN) {
            kv = g_K[gn * OUTD + h * 32 + dcol];
            vv = g_V[gn * OUTD + h * 32 + dcol];
        }
        k_s[n][dcol] = kv;
        v_s[n][dcol] = vv;
        vt_s[n][dcol] = vv + time_emb[h * 32 + dcol];
    }
    for (int idx = tid; idx < 32; idx += 288) {
        int gn = nodeBase + idx;
        ct_s[idx] = (gn < NN) ? cau_type[gn] : -1;
    }
    __syncthreads();

    int wid = tid >> 5, lane = tid & 31;
    const float* mat;
    const float (*srcm)[32];
    __half* outp;
    int myct = -1;
    if (wid < 3) {
        mat = cau_filter + (wid * NH + h) * 1024;
        srcm = k_s; outp = g_KMh + 256; myct = wid;          // mk half of KM row
    } else if (wid < 6) {
        int e = wid - 3;
        mat = msg + (e * NH + h) * 1024;
        srcm = v_s; outp = g_VC + (size_t)e * NN * 512;      // val at offset 0
    } else {
        int e = wid - 6;
        mat = msg_cau + (e * NH + h) * 1024;
        srcm = vt_s; outp = g_VC + (size_t)e * NN * 512 + 256;  // cval at +256
    }

    ull m2[16];
#pragma unroll
    for (int i = 0; i < 16; i++)
        m2[i] = pack2(mat[(2 * i) * 32 + lane], mat[(2 * i + 1) * 32 + lane]);

    for (int n = 0; n < 32; n++) {
        int gn = nodeBase + n;
        if (gn >= NN) break;
        if (myct >= 0 && ct_s[n] != myct) continue;
        ull acc = 0ull;
        const ull* row = (const ull*)&srcm[n][0];
#pragma unroll
        for (int i = 0; i < 16; i++)
            fma2(acc, row[i], m2[i]);
        float2 f = unpack2(acc);
        outp[(size_t)gn * 512 + h * 32 + lane] = __float2half(f.x + f.y);
    }
}

// ---------------- kernel 3: edge logits + softmax denominators ----------------
// Q fp32 (2x LDG.128), k/mk fp16 from one interleaved row (4x LDG.64, 8 F2F).
// Parity-packed butterfly reduction (R12), identical E/S write pattern.
__global__ void __launch_bounds__(256) logits_kernel(
    const int* __restrict__ src, const int* __restrict__ dst,
    const float* __restrict__ pri, const float* __restrict__ pri_cau)
{
    int e = blockIdx.y;
    int edge = blockIdx.x * 8 + (threadIdx.x >> 5);
    if (edge >= EE) return;
    int lane = threadIdx.x & 31;
    int s = src[e * EE + edge];
    int d = dst[e * EE + edge];
    int off = lane * 4;

    const float* qp = g_Q + d * OUTD;
    const __half* kmp = g_KMh + (size_t)s * 512;
    float4 qa = *(const float4*)(qp + off);
    float4 qb = *(const float4*)(qp + 128 + off);
    float4 ka = h4_to_f4(*(const uint2*)(kmp + off));
    float4 kb = h4_to_f4(*(const uint2*)(kmp + 128 + off));
    float4 ma = h4_to_f4(*(const uint2*)(kmp + 256 + off));
    float4 mb = h4_to_f4(*(const uint2*)(kmp + 384 + off));

    float p0 = dot4(qa, ka);
    float p1 = dot4(qb, kb);
    float m0 = dot4(qa, ma);
    float m1 = dot4(qb, mb);

    int odd = lane & 1;
    float pv = odd ? p0 : p1;
    float mv = odd ? m0 : m1;
    float pr = __shfl_xor_sync(0xffffffffu, pv, 1);
    float mr = __shfl_xor_sync(0xffffffffu, mv, 1);
    float P = (odd ? p1 : p0) + pr;
    float M = (odd ? m1 : m0) + mr;
    P += __shfl_xor_sync(0xffffffffu, P, 2);
    M += __shfl_xor_sync(0xffffffffu, M, 2);
    P += __shfl_xor_sync(0xffffffffu, P, 4);
    M += __shfl_xor_sync(0xffffffffu, M, 4);

    int hh = (lane >> 3) + (odd << 2);
    const float isdk = 0.17677669529663687f;  // 1/sqrt(32)
    float ea = __expf(P * pri[e * NH + hh] * isdk);
    float ec = __expf(M * pri_cau[e * NH + hh] * isdk);

    int srcl = (lane & 3) * 8 + ((lane >> 2) & 1);
    float va = __shfl_sync(0xffffffffu, ea, srcl);
    float vc = __shfl_sync(0xffffffffu, ec, srcl);

    if (lane < NH) {
        int eidx = e * EE + edge;
        g_E[eidx * NH + lane] = make_float2(va, vc);
        red_add_v2(&g_S[(e * NN + d) * NH + lane], va, vc);
    }
}

// ---------------- kernel 4: weighted aggregation (fp16 VC gathers) ----------------
__global__ void __launch_bounds__(256) aggregate_kernel(
    const int* __restrict__ src, const int* __restrict__ dst,
    const float* __restrict__ comb_pri, float* __restrict__ out)
{
    int e = blockIdx.y;
    int edge = blockIdx.x * 8 + (threadIdx.x >> 5);
    if (edge >= EE) return;
    int lane = threadIdx.x & 31;
    int s = src[e * EE + edge];
    int d = dst[e * EE + edge];
    int h0 = lane >> 3;
    int h1 = h0 + 4;
    int eidx = e * EE + edge;

    float2 eh0 = g_E[eidx * NH + h0];
    float2 eh1 = g_E[eidx * NH + h1];
    float2 s0 = g_S[(e * NN + d) * NH + h0];
    float2 s1 = g_S[(e * NN + d) * NH + h1];
    float wa0 = __fdividef(eh0.x, s0.x);
    float wc0 = __fdividef(eh0.y, s0.y);
    float wa1 = __fdividef(eh1.x, s1.x);
    float wc1 = __fdividef(eh1.y, s1.y);

    int off = lane * 4;
    const __half* vp = g_VC + ((size_t)e * NN + s) * 512;
    float4 v0 = h4_to_f4(*(const uint2*)(vp + off));
    float4 v1 = h4_to_f4(*(const uint2*)(vp + 128 + off));
    float4 c0 = h4_to_f4(*(const uint2*)(vp + 256 + off));
    float4 c1 = h4_to_f4(*(const uint2*)(vp + 384 + off));
    float4 b0 = *(const float4*)&comb_pri[e * OUTD + off];
    float4 b1 = *(const float4*)&comb_pri[e * OUTD + 128 + off];

    float r0 = wa0 * v0.x + wc0 * b0.x * c0.x;
    float r1 = wa0 * v0.y + wc0 * b0.y * c0.y;
    float r2 = wa0 * v0.z + wc0 * b0.z * c0.z;
    float r3 = wa0 * v0.w + wc0 * b0.w * c0.w;
    float r4 = wa1 * v1.x + wc1 * b1.x * c1.x;
    float r5 = wa1 * v1.y + wc1 * b1.y * c1.y;
    float r6 = wa1 * v1.z + wc1 * b1.z * c1.z;
    float r7 = wa1 * v1.w + wc1 * b1.w * c1.w;

    float* op = out + d * OUTD;
    red_add_v4(op + off, r0, r1, r2, r3);
    red_add_v4(op + 128 + off, r4, r5, r6, r7);
}

// ---------------- kernel 5: finalize (mean over 3 etypes + relu) ----------------
__global__ void finalize_kernel(float* __restrict__ out) {
    int i = blockIdx.x * blockDim.x + threadIdx.x;
    if (i < NN * OUTD) {
        float v = out[i] * (1.0f / 3.0f);
        out[i] = v > 0.0f ? v : 0.0f;
    }
}

// ---------------- launch ----------------
extern "C" void kernel_launch(void* const* d_in, const int* in_sizes, int n_in,
                              void* d_out, int out_size) {
    const float* x          = (const float*)d_in[0];
    const float* Wk         = (const float*)d_in[1];
    const float* bk         = (const float*)d_in[2];
    const float* Wq         = (const float*)d_in[3];
    const float* bq         = (const float*)d_in[4];
    const float* Wv         = (const float*)d_in[5];
    const float* bv         = (const float*)d_in[6];
    const float* pri        = (const float*)d_in[7];
    const float* msg        = (const float*)d_in[8];
    const float* pri_cau    = (const float*)d_in[9];
    const float* msg_cau    = (const float*)d_in[10];
    const float* comb_pri   = (const float*)d_in[11];
    const float* cau_filter = (const float*)d_in[12];
    const float* time_emb   = (const float*)d_in[13];
    const int*   cau_type   = (const int*)d_in[14];
    const int*   src        = (const int*)d_in[15];
    const int*   dst        = (const int*)d_in[16];
    float* out = (float*)d_out;

    split_x_kernel<<<(NN * INDIM / 4 + 255) / 256, 256>>>(x);
    split_w_kernel<<<768, 256>>>(Wk, Wq, Wv);

    cudaFuncSetAttribute(gemm_mma, cudaFuncAttributeMaxDynamicSharedMemorySize,
                         2 * STAGE_BYTES);
    gemm_mma<<<dim3(6, 157), 256, 2 * STAGE_BYTES>>>(bk, bq, bv);

    dim3 tgrid((NN + 31) / 32, NH);
    transform_kernel<<<tgrid, 288>>>(msg, msg_cau, cau_filter, time_emb, cau_type, out);

    dim3 egrid((EE + 7) / 8, 3);
    logits_kernel<<<egrid, 256>>>(src, dst, pri, pri_cau);
    aggregate_kernel<<<egrid, 256>>>(src, dst, comb_pri, out);

    finalize_kernel<<<(NN * OUTD + 255) / 256, 256>>>(out);
}